// round 7
// baseline (speedup 1.0000x reference)
#include <cuda_runtime.h>
#include <math.h>

#define Bn 16
#define Cn 64
#define Hn 256
#define HWn 65536

__device__ float g_x[Bn*Cn*HWn];       // activations [b][c][h][w] (in place)
__device__ float g_G[Bn*Cn*Hn*32];     // fwd w-DFT: [bc][h][kx](re,im)
__device__ float g_F[Bn*Cn*1024];      // fwd spectrum [bc][s][kx][2]
__device__ float g_F2[Bn*Cn*1024];     // after spectral mix [bo][s][kx][2]
__device__ float g_Gi[Bn*Cn*8192];     // inv h-DFT [bo][kx][h](re,im) interleaved
__device__ float g_part[Bn*Cn*256];    // proj partial sums per (b,o,h)
__device__ float g_ct[256];
__device__ float g_st[256];
__device__ float2 g_cc2[256];
__device__ float2 g_ss2[256];

__device__ __forceinline__ float gelu(float x) {
    return 0.5f * x * (1.0f + erff(x * 0.70710678f));
}

__device__ __forceinline__ float2 ffma2(float2 a, float2 b, float2 c) {
    float2 d;
    asm("fma.rn.f32x2 %0, %1, %2, %3;"
        : "=l"(*(unsigned long long*)&d)
        : "l"(*(unsigned long long*)&a),
          "l"(*(unsigned long long*)&b),
          "l"(*(unsigned long long*)&c));
    return d;
}

// ---------------- compile-time twiddles (forced constant-fold) ----------------
constexpr double TPI_ = 3.141592653589793238462643383279502884;
constexpr double tcos_(double x) {
    double t = 1.0, s = 1.0;
    for (int i = 1; i <= 16; i++) { t = -t * x * x / ((2.0 * i - 1.0) * (2.0 * i)); s += t; }
    return s;
}
constexpr double tsin_(double x) {
    double t = x, s = x;
    for (int i = 1; i <= 16; i++) { t = -t * x * x / ((2.0 * i) * (2.0 * i + 1.0)); s += t; }
    return s;
}
constexpr double ang_(int n) { return ((n <= 128) ? n : n - 256) * (TPI_ / 128.0); }
template<int N> struct TwN {
    static constexpr float C = (float)tcos_(ang_(N));      // cos(2pi N/256)
    static constexpr float S = (float)(-tsin_(ang_(N)));   // -sin(2pi N/256)
};

// acc[k] += x * e^{-2pi i (W*k)/256}, twiddles immediate, 16 modes
template<int W, int K> struct KL {
    static __device__ __forceinline__ void run(float x, float2* a) {
        constexpr int N = (W * K) & 255;
        a[K].x = fmaf(x, TwN<N>::C, a[K].x);
        a[K].y = fmaf(x, TwN<N>::S, a[K].y);
        KL<W, K + 1>::run(x, a);
    }
};
template<int W> struct KL<W, 16> {
    static __device__ __forceinline__ void run(float, float2*) {}
};
// 64 consecutive w positions starting at compile-time W0, loaded as float4
template<int W0, int J> struct JL4 {
    static __device__ __forceinline__ void run(const float* xr, float2* a) {
        float4 v = *(const float4*)&xr[J];
        KL<W0 + J + 0, 0>::run(v.x, a);
        KL<W0 + J + 1, 0>::run(v.y, a);
        KL<W0 + J + 2, 0>::run(v.z, a);
        KL<W0 + J + 3, 0>::run(v.w, a);
        JL4<W0, J + 4>::run(xr, a);
    }
};
template<int W0> struct JL4<W0, 64> {
    static __device__ __forceinline__ void run(const float*, float2*) {}
};

// ---------------- in-block row-DFT phase ----------------
// xs holds the row: xs[c*264 + w], c=0..63, w=0..255. 256 threads = 64 c x 4 w-quarters.
// Writes g_G[((b*64+c)*256+h)*32 + 2k..]. DESTROYS xs (partials stored there).
__device__ __forceinline__ void dft_phase(float* xs, int tid, int b, int h) {
    int q = tid >> 6, c = tid & 63;
    float2 a2[16];
    #pragma unroll
    for (int k = 0; k < 16; k++) a2[k] = make_float2(0.f, 0.f);
    const float* xr = xs + c * 264 + q * 64;
    if      (q == 0) JL4<0,   0>::run(xr, a2);
    else if (q == 1) JL4<64,  0>::run(xr, a2);
    else if (q == 2) JL4<128, 0>::run(xr, a2);
    else             JL4<192, 0>::run(xr, a2);
    __syncthreads();                      // all xs reads done -> safe to overwrite
    float2* pd = (float2*)xs;             // partials [c*16+k][q]
    #pragma unroll
    for (int k = 0; k < 16; k++) pd[(c * 16 + k) * 4 + q] = a2[k];
    __syncthreads();
    float2* go = (float2*)g_G;
    #pragma unroll
    for (int u = 0; u < 4; u++) {
        int p = tid * 4 + u;
        int cc = p >> 4, k = p & 15;
        float2 s0 = pd[p * 4], s1 = pd[p * 4 + 1], s2 = pd[p * 4 + 2], s3 = pd[p * 4 + 3];
        go[((b * 64 + cc) * 256 + h) * 16 + k] =
            make_float2(s0.x + s1.x + s2.x + s3.x, s0.y + s1.y + s2.y + s3.y);
    }
}

// ---------------- init: fp32 twiddle tables ----------------
__global__ void k_init() {
    int tid = threadIdx.x;
    double s, c;
    sincospi((double)tid / 128.0, &s, &c);
    g_ct[tid] = (float)c;  g_st[tid] = (float)s;
    g_cc2[tid] = make_float2((float)c, (float)c);
    g_ss2[tid] = make_float2((float)s, (float)s);
}

// ---------------- lift + fwd w-DFT fused ----------------
__global__ void __launch_bounds__(256) k_lift_fw(const float* __restrict__ grid,
                                                 const float* __restrict__ lw,
                                                 const float* __restrict__ lb) {
    extern __shared__ float xs[];          // 64*264 floats
    __shared__ float sw[960], sb[64];
    int tid = threadIdx.x;
    int b = blockIdx.x >> 8, h = blockIdx.x & 255;
    for (int i = tid; i < 960; i += 256) sw[i] = lw[i];
    if (tid < 64) sb[tid] = lb[tid];
    __syncthreads();
    float in[15];
    const float* gp = grid + b * 15 * HWn + h * 256 + tid;
    #pragma unroll
    for (int c = 0; c < 15; c++) in[c] = gp[c * HWn];
    float* xp = g_x + b * 64 * HWn + h * 256 + tid;
    for (int o = 0; o < 64; o++) {
        float a = sb[o];
        #pragma unroll
        for (int c = 0; c < 15; c++) a = fmaf(in[c], sw[o * 15 + c], a);
        float v = gelu(a);
        xp[o * HWn] = v;
        xs[o * 264 + tid] = v;
    }
    __syncthreads();
    dft_phase(xs, tid, b, h);
}

// ---------------- fwd h-DFT (R2 scalar, measured 43.9us) ----------------
__global__ void __launch_bounds__(256) k_fwd_h() {
    __shared__ float Gs[8192];
    int tid = threadIdx.x, bc = blockIdx.x;
    const float* gp = g_G + bc * 8192;
    for (int i = tid; i < 8192; i += 256) Gs[i] = gp[i];
    __syncthreads();
    int s = tid >> 3, kq = tid & 7;
    int ky = (s < 16) ? s : s + 224;
    float cd = g_ct[ky], sd = -g_st[ky], cw = 1.f, sw = 0.f;
    float fr0 = 0.f, fi0 = 0.f, fr1 = 0.f, fi1 = 0.f;
    for (int h = 0; h < 256; h++) {
        float2 g0 = *(const float2*)&Gs[h * 32 + kq * 4];
        float2 g1 = *(const float2*)&Gs[h * 32 + kq * 4 + 2];
        fr0 = fmaf(g0.x, cw, fmaf(-g0.y, sw, fr0));
        fi0 = fmaf(g0.y, cw, fmaf( g0.x, sw, fi0));
        fr1 = fmaf(g1.x, cw, fmaf(-g1.y, sw, fr1));
        fi1 = fmaf(g1.y, cw, fmaf( g1.x, sw, fi1));
        float cn = cw * cd - sw * sd;
        sw = fmaf(cw, sd, sw * cd);  cw = cn;
    }
    int base = bc * 1024 + (s * 16 + kq * 2) * 2;
    g_F[base] = fr0; g_F[base + 1] = fi0; g_F[base + 2] = fr1; g_F[base + 3] = fi1;
}

// ---------------- spectral multiply (R2 scalar) ----------------
__global__ void __launch_bounds__(256) k_spec(const float* __restrict__ w1r, const float* __restrict__ w1i,
                                              const float* __restrict__ w2r, const float* __restrict__ w2i,
                                              int l) {
    __shared__ float Wr[4096], Wi[4096], Ar[1024], Ai[1024];
    int s = blockIdx.x >> 4, kx = blockIdx.x & 15;
    int m = (s < 16) ? s : s - 16;
    long off = (long)l * Cn * Cn * 256 + m * 16 + kx;
    const float* wr = ((s < 16) ? w1r : w2r) + off;
    const float* wi = ((s < 16) ? w1i : w2i) + off;
    for (int t = threadIdx.x; t < 4096; t += 256) { Wr[t] = wr[(long)t * 256]; Wi[t] = wi[(long)t * 256]; }
    int mo = (s * 16 + kx) * 2;
    for (int t = threadIdx.x; t < 1024; t += 256) { Ar[t] = g_F[t * 1024 + mo]; Ai[t] = g_F[t * 1024 + mo + 1]; }
    __syncthreads();
    int o = threadIdx.x & 63, bq = threadIdx.x >> 6;
    float orr[4], oii[4];
    #pragma unroll
    for (int u = 0; u < 4; u++) { orr[u] = 0.f; oii[u] = 0.f; }
    for (int i = 0; i < 64; i++) {
        float wrv = Wr[i * 64 + o], wiv = Wi[i * 64 + o];
        #pragma unroll
        for (int u = 0; u < 4; u++) {
            float arv = Ar[(bq * 4 + u) * 64 + i], aiv = Ai[(bq * 4 + u) * 64 + i];
            orr[u] = fmaf(arv, wrv, fmaf(-aiv, wiv, orr[u]));
            oii[u] = fmaf(arv, wiv, fmaf( aiv, wrv, oii[u]));
        }
    }
    #pragma unroll
    for (int u = 0; u < 4; u++) {
        int b = bq * 4 + u;
        g_F2[(b * 64 + o) * 1024 + mo]     = orr[u];
        g_F2[(b * 64 + o) * 1024 + mo + 1] = oii[u];
    }
}

// ---------------- inv h-DFT (packed, interleaved float2 output) ----------------
__global__ void __launch_bounds__(256) k_inv_h() {
    __shared__ float Fs[1024];
    __shared__ float2 scc[256], sss[256];
    int tid = threadIdx.x, bo = blockIdx.x;
    const float* fp = g_F2 + bo * 1024;
    for (int i = tid; i < 1024; i += 256) Fs[i] = fp[i];
    scc[tid] = g_cc2[tid]; sss[tid] = g_ss2[tid];
    __syncthreads();
    int h = tid;
    float2 P[16], Q[16];
    #pragma unroll
    for (int k = 0; k < 16; k++) { P[k] = make_float2(0.f, 0.f); Q[k] = make_float2(0.f, 0.f); }
    #pragma unroll 2
    for (int s = 0; s < 32; s++) {
        int ky = (s < 16) ? s : s + 224;
        int idx = (ky * h) & 255;
        float2 cc = scc[idx], ss = sss[idx];
        #pragma unroll
        for (int q = 0; q < 8; q++) {
            float4 f4 = *(const float4*)&Fs[s * 32 + q * 4];
            float2 fa = make_float2(f4.x, f4.y), fb = make_float2(f4.z, f4.w);
            P[2 * q]     = ffma2(fa, cc, P[2 * q]);     Q[2 * q]     = ffma2(fa, ss, Q[2 * q]);
            P[2 * q + 1] = ffma2(fb, cc, P[2 * q + 1]); Q[2 * q + 1] = ffma2(fb, ss, Q[2 * q + 1]);
        }
    }
    float2* go = (float2*)g_Gi + bo * 4096 + h;
    #pragma unroll
    for (int k = 0; k < 16; k++) {
        float sc = (k == 0 ? 1.f : 2.f) * (1.f / 65536.f);
        go[k * 256] = make_float2((P[k].x - Q[k].y) * sc, (P[k].y + Q[k].x) * sc);
    }
}

// ---------------- fused inv w-DFT + skip conv + BN + gelu + residual + NEXT-LAYER fwd w-DFT ----------------
__global__ void __launch_bounds__(256, 2) k_fuse_fw(const float* __restrict__ skw, const float* __restrict__ skb,
                                                    const float* __restrict__ bng, const float* __restrict__ bnb,
                                                    const float* __restrict__ bnm, const float* __restrict__ bnv,
                                                    int l, int do_dft) {
    extern __shared__ float sm[];
    float* xs   = sm;              // 16896 = 64*264
    float* swt  = xs + 16896;      // 4096: [c][o]
    float* gis  = swt + 4096;      // 2048: [kx][ri][o], ri=1 negated
    float* ctb  = gis + 2048;      // 256
    float* stb  = ctb + 256;       // 256
    float* bnA  = stb + 256;       // 64
    float* bnB  = bnA + 64;        // 64
    float* sbbv = bnB + 64;        // 64
    int tid = threadIdx.x;
    int b = blockIdx.x >> 8, h = blockIdx.x & 255;
    float* xp = g_x + b * 64 * HWn + h * 256;
    for (int c = 0; c < 64; c++) xs[c * 264 + tid] = xp[c * HWn + tid];
    for (int i = tid; i < 4096; i += 256) {
        int o = i >> 6, c = i & 63;
        swt[c * 64 + o] = skw[l * 4096 + i];
    }
    for (int i = tid; i < 1024; i += 256) {
        int o = i >> 4, kx = i & 15;
        float2 v = ((const float2*)g_Gi)[(b * 64 + o) * 4096 + kx * 256 + h];
        gis[(kx * 2) * 64 + o]     = v.x;
        gis[(kx * 2 + 1) * 64 + o] = -v.y;
    }
    ctb[tid] = g_ct[tid];  stb[tid] = g_st[tid];
    if (tid < 64) {
        float A = bng[l * 64 + tid] * rsqrtf(bnv[l * 64 + tid] + 1e-5f);
        bnA[tid] = A;
        bnB[tid] = fmaf(-bnm[l * 64 + tid], A, bnb[l * 64 + tid]);
        sbbv[tid] = skb[l * 64 + tid];
    }
    __syncthreads();
    int wb = (tid & 63) * 4, ob = (tid >> 6) * 16;
    float2 acc[8][4];
    #pragma unroll
    for (int ip = 0; ip < 8; ip++) {
        float2 bias = *(const float2*)&sbbv[ob + ip * 2];
        acc[ip][0] = bias; acc[ip][1] = bias; acc[ip][2] = bias; acc[ip][3] = bias;
    }
    // skip conv (o-pair packed)
    for (int c = 0; c < 64; c++) {
        float4 xv = *(const float4*)&xs[c * 264 + wb];
        float2 x0 = make_float2(xv.x, xv.x), x1 = make_float2(xv.y, xv.y);
        float2 x2 = make_float2(xv.z, xv.z), x3 = make_float2(xv.w, xv.w);
        #pragma unroll
        for (int ip = 0; ip < 8; ip++) {
            float2 wv = *(const float2*)&swt[c * 64 + ob + ip * 2];
            acc[ip][0] = ffma2(x0, wv, acc[ip][0]);
            acc[ip][1] = ffma2(x1, wv, acc[ip][1]);
            acc[ip][2] = ffma2(x2, wv, acc[ip][2]);
            acc[ip][3] = ffma2(x3, wv, acc[ip][3]);
        }
    }
    // inverse w-DFT via per-thread twiddle recurrence over kx
    float dc[4], ds[4], tc_[4], ts_[4];
    #pragma unroll
    for (int j = 0; j < 4; j++) {
        dc[j] = ctb[wb + j];  ds[j] = stb[wb + j];
        tc_[j] = 1.f;  ts_[j] = 0.f;
    }
    #pragma unroll 4
    for (int kx = 0; kx < 16; kx++) {
        float2 cc0 = make_float2(tc_[0], tc_[0]), ss0 = make_float2(ts_[0], ts_[0]);
        float2 cc1 = make_float2(tc_[1], tc_[1]), ss1 = make_float2(ts_[1], ts_[1]);
        float2 cc2 = make_float2(tc_[2], tc_[2]), ss2 = make_float2(ts_[2], ts_[2]);
        float2 cc3 = make_float2(tc_[3], tc_[3]), ss3 = make_float2(ts_[3], ts_[3]);
        #pragma unroll
        for (int ip = 0; ip < 8; ip++) {
            float2 gr = *(const float2*)&gis[(kx * 2) * 64 + ob + ip * 2];
            float2 gi = *(const float2*)&gis[(kx * 2 + 1) * 64 + ob + ip * 2];
            acc[ip][0] = ffma2(gr, cc0, acc[ip][0]);  acc[ip][0] = ffma2(gi, ss0, acc[ip][0]);
            acc[ip][1] = ffma2(gr, cc1, acc[ip][1]);  acc[ip][1] = ffma2(gi, ss1, acc[ip][1]);
            acc[ip][2] = ffma2(gr, cc2, acc[ip][2]);  acc[ip][2] = ffma2(gi, ss2, acc[ip][2]);
            acc[ip][3] = ffma2(gr, cc3, acc[ip][3]);  acc[ip][3] = ffma2(gi, ss3, acc[ip][3]);
        }
        #pragma unroll
        for (int j = 0; j < 4; j++) {
            float nc = tc_[j] * dc[j] - ts_[j] * ds[j];
            ts_[j] = fmaf(tc_[j], ds[j], ts_[j] * dc[j]);
            tc_[j] = nc;
        }
    }
    // epilogue: BN + gelu + residual; write global; stash new values back into acc
    #pragma unroll
    for (int ip = 0; ip < 8; ip++) {
        int o0 = ob + ip * 2, o1 = o0 + 1;
        float A0 = bnA[o0], B0 = bnB[o0], A1 = bnA[o1], B1 = bnB[o1];
        float4 r0, r1;
        r0.x = gelu(fmaf(acc[ip][0].x, A0, B0)) + xs[o0 * 264 + wb];
        r0.y = gelu(fmaf(acc[ip][1].x, A0, B0)) + xs[o0 * 264 + wb + 1];
        r0.z = gelu(fmaf(acc[ip][2].x, A0, B0)) + xs[o0 * 264 + wb + 2];
        r0.w = gelu(fmaf(acc[ip][3].x, A0, B0)) + xs[o0 * 264 + wb + 3];
        r1.x = gelu(fmaf(acc[ip][0].y, A1, B1)) + xs[o1 * 264 + wb];
        r1.y = gelu(fmaf(acc[ip][1].y, A1, B1)) + xs[o1 * 264 + wb + 1];
        r1.z = gelu(fmaf(acc[ip][2].y, A1, B1)) + xs[o1 * 264 + wb + 2];
        r1.w = gelu(fmaf(acc[ip][3].y, A1, B1)) + xs[o1 * 264 + wb + 3];
        *(float4*)&xp[o0 * HWn + wb] = r0;
        *(float4*)&xp[o1 * HWn + wb] = r1;
        acc[ip][0] = make_float2(r0.x, r1.x);
        acc[ip][1] = make_float2(r0.y, r1.y);
        acc[ip][2] = make_float2(r0.z, r1.z);
        acc[ip][3] = make_float2(r0.w, r1.w);
    }
    if (do_dft) {
        __syncthreads();   // all residual reads of old xs complete
        #pragma unroll
        for (int ip = 0; ip < 8; ip++) {
            int o0 = ob + ip * 2, o1 = o0 + 1;
            #pragma unroll
            for (int j = 0; j < 4; j++) {
                xs[o0 * 264 + wb + j] = acc[ip][j].x;
                xs[o1 * 264 + wb + j] = acc[ip][j].y;
            }
        }
        __syncthreads();
        dft_phase(xs, tid, b, h);
    }
}

// ---------------- proj conv + gelu + partial mean (R2 scalar) ----------------
__global__ void __launch_bounds__(256) k_proj(const float* __restrict__ pw, const float* __restrict__ pb) {
    __shared__ float pws[4096], pbs[64], wsum[64][8];
    int tid = threadIdx.x;
    int b = blockIdx.x >> 8, h = blockIdx.x & 255;
    for (int i = tid; i < 4096; i += 256) pws[i] = pw[i];
    if (tid < 64) pbs[tid] = pb[tid];
    __syncthreads();
    const float* xp = g_x + b * 64 * HWn + h * 256 + tid;
    float xv[64];
    #pragma unroll
    for (int c = 0; c < 64; c++) xv[c] = xp[c * HWn];
    int lane = tid & 31, wid = tid >> 5;
    for (int o = 0; o < 64; o++) {
        float a = pbs[o];
        #pragma unroll
        for (int c = 0; c < 64; c++) a = fmaf(xv[c], pws[o * 64 + c], a);
        a = gelu(a);
        #pragma unroll
        for (int off = 16; off; off >>= 1) a += __shfl_down_sync(0xffffffffu, a, off);
        if (lane == 0) wsum[o][wid] = a;
    }
    __syncthreads();
    if (tid < 64) {
        float s = 0.f;
        #pragma unroll
        for (int j = 0; j < 8; j++) s += wsum[tid][j];
        g_part[(b * 64 + tid) * 256 + h] = s;
    }
}

__global__ void __launch_bounds__(128) k_head(const float* __restrict__ env, const float* __restrict__ d1d,
    const float* __restrict__ dw1, const float* __restrict__ db1,
    const float* __restrict__ dw2, const float* __restrict__ db2,
    const float* __restrict__ dw3, const float* __restrict__ db3,
    const float* __restrict__ iw1, const float* __restrict__ ib1,
    const float* __restrict__ iw2, const float* __restrict__ ib2,
    const float* __restrict__ iw3, const float* __restrict__ ib3,
    float* __restrict__ out) {
    __shared__ float feat[108], h1[128], h2[64];
    int b = blockIdx.x, t = threadIdx.x;
    if (t < 64) {
        float s = 0.f;
        const float* pp = g_part + (b * 64 + t) * 256;
        for (int h = 0; h < 256; h++) s += pp[h];
        feat[t] = s * (1.0f / 65536.0f);
    } else if (t < 104) feat[t] = env[b * 40 + t - 64];
    else if (t < 108)   feat[t] = d1d[b * 4 + t - 104];
    __syncthreads();
    { float a = db1[t];
      for (int k = 0; k < 108; k++) a = fmaf(feat[k], dw1[t * 108 + k], a);
      h1[t] = gelu(a); }
    __syncthreads();
    if (t < 64) { float a = db2[t];
      for (int k = 0; k < 128; k++) a = fmaf(h1[k], dw2[t * 128 + k], a);
      h2[t] = gelu(a); }
    __syncthreads();
    if (t < 8) { float a = db3[t];
      for (int k = 0; k < 64; k++) a = fmaf(h2[k], dw3[t * 64 + k], a);
      out[b * 8 + t] = a; }
    __syncthreads();
    { float a = ib1[t];
      for (int k = 0; k < 108; k++) a = fmaf(feat[k], iw1[t * 108 + k], a);
      h1[t] = gelu(a); }
    __syncthreads();
    if (t < 64) { float a = ib2[t];
      for (int k = 0; k < 128; k++) a = fmaf(h1[k], iw2[t * 128 + k], a);
      h2[t] = gelu(a); }
    __syncthreads();
    if (t < 4) { float a = ib3[t];
      for (int k = 0; k < 64; k++) a = fmaf(h2[k], iw3[t * 64 + k], a);
      out[128 + b * 4 + t] = a; }
}

extern "C" void kernel_launch(void* const* d_in, const int* in_sizes, int n_in,
                              void* d_out, int out_size) {
    const float* grid_in = (const float*)d_in[0];
    const float* env  = (const float*)d_in[1];
    const float* d1d  = (const float*)d_in[2];
    const float* lw   = (const float*)d_in[3];
    const float* lb   = (const float*)d_in[4];
    const float* w1r  = (const float*)d_in[5];
    const float* w1i  = (const float*)d_in[6];
    const float* w2r  = (const float*)d_in[7];
    const float* w2i  = (const float*)d_in[8];
    const float* skw  = (const float*)d_in[9];
    const float* skb  = (const float*)d_in[10];
    const float* bng  = (const float*)d_in[11];
    const float* bnb  = (const float*)d_in[12];
    const float* bnm  = (const float*)d_in[13];
    const float* bnv  = (const float*)d_in[14];
    const float* pw   = (const float*)d_in[15];
    const float* pb   = (const float*)d_in[16];
    const float* dw1  = (const float*)d_in[17];
    const float* db1  = (const float*)d_in[18];
    const float* dw2  = (const float*)d_in[19];
    const float* db2  = (const float*)d_in[20];
    const float* dw3  = (const float*)d_in[21];
    const float* db3  = (const float*)d_in[22];
    const float* iw1  = (const float*)d_in[23];
    const float* ib1  = (const float*)d_in[24];
    const float* iw2  = (const float*)d_in[25];
    const float* ib2  = (const float*)d_in[26];
    const float* iw3  = (const float*)d_in[27];
    const float* ib3  = (const float*)d_in[28];
    float* out = (float*)d_out;

    static bool attr_done = false;
    if (!attr_done) {
        cudaFuncSetAttribute(k_lift_fw, cudaFuncAttributeMaxDynamicSharedMemorySize, 67584);
        cudaFuncSetAttribute(k_fuse_fw, cudaFuncAttributeMaxDynamicSharedMemorySize, 94976);
        attr_done = true;
    }

    k_init<<<1, 256>>>();
    k_lift_fw<<<4096, 256, 67584>>>(grid_in, lw, lb);
    for (int l = 0; l < 4; l++) {
        k_fwd_h<<<1024, 256>>>();
        k_spec<<<512, 256>>>(w1r, w1i, w2r, w2i, l);
        k_inv_h<<<1024, 256>>>();
        k_fuse_fw<<<4096, 256, 94976>>>(skw, skb, bng, bnb, bnm, bnv, l, (l < 3) ? 1 : 0);
    }
    k_proj<<<4096, 256>>>(pw, pb);
    k_head<<<16, 128>>>(env, d1d, dw1, db1, dw2, db2, dw3, db3,
                        iw1, ib1, iw2, ib2, iw3, ib3, out);
}

// round 8
// speedup vs baseline: 1.2388x; 1.2388x over previous
#include <cuda_runtime.h>
#include <math.h>

#define Bn 16
#define Cn 64
#define Hn 256
#define HWn 65536

__device__ float g_x[Bn*Cn*HWn];       // activations [b][c][h][w] (in place)
__device__ float g_G[Bn*Cn*Hn*32];     // fwd w-DFT: [bc*256+h][kx](re,im)
__device__ float g_F[512*2048];        // fwd spectrum, mode-major: [mode][re|im][bc]
__device__ float g_F2[Bn*Cn*1024];     // after spectral mix [bo][mode][2]
__device__ float g_Gi[Bn*Cn*8192];     // inv h-DFT [bo][kx][h](re,im) interleaved
__device__ float g_part[Bn*Cn*256];    // proj partial sums per (b,o,h)
__device__ float g_ct[256];
__device__ float g_st[256];
__device__ float2 g_cc2[256];
__device__ float2 g_ss2[256];
__device__ float g_Wtr[4*512*4096];    // transposed weights: [l][mode][i*64+o]
__device__ float g_Wti[4*512*4096];

__device__ __forceinline__ float gelu(float x) {
    return 0.5f * x * (1.0f + erff(x * 0.70710678f));
}

__device__ __forceinline__ float2 ffma2(float2 a, float2 b, float2 c) {
    float2 d;
    asm("fma.rn.f32x2 %0, %1, %2, %3;"
        : "=l"(*(unsigned long long*)&d)
        : "l"(*(unsigned long long*)&a),
          "l"(*(unsigned long long*)&b),
          "l"(*(unsigned long long*)&c));
    return d;
}

// ---------------- compile-time twiddles (forced constant-fold) ----------------
constexpr double TPI_ = 3.141592653589793238462643383279502884;
constexpr double tcos_(double x) {
    double t = 1.0, s = 1.0;
    for (int i = 1; i <= 16; i++) { t = -t * x * x / ((2.0 * i - 1.0) * (2.0 * i)); s += t; }
    return s;
}
constexpr double tsin_(double x) {
    double t = x, s = x;
    for (int i = 1; i <= 16; i++) { t = -t * x * x / ((2.0 * i) * (2.0 * i + 1.0)); s += t; }
    return s;
}
constexpr double ang_(int n) { return ((n <= 128) ? n : n - 256) * (TPI_ / 128.0); }
template<int N> struct TwN {
    static constexpr float C = (float)tcos_(ang_(N));      // cos(2pi N/256)
    static constexpr float S = (float)(-tsin_(ang_(N)));   // -sin(2pi N/256)
};

template<int W, int K> struct KL {
    static __device__ __forceinline__ void run(float x, float2* a) {
        constexpr int N = (W * K) & 255;
        a[K].x = fmaf(x, TwN<N>::C, a[K].x);
        a[K].y = fmaf(x, TwN<N>::S, a[K].y);
        KL<W, K + 1>::run(x, a);
    }
};
template<int W> struct KL<W, 16> {
    static __device__ __forceinline__ void run(float, float2*) {}
};
template<int W0, int J> struct JL {
    static __device__ __forceinline__ void run(const float* xr, float2* a) {
        KL<W0 + J, 0>::run(xr[J], a);
        JL<W0, J + 1>::run(xr, a);
    }
};
template<int W0> struct JL<W0, 32> {
    static __device__ __forceinline__ void run(const float*, float2*) {}
};

template<int CC>
__device__ __forceinline__ void fw_chunk(int tid, int r0, float* xs, float2* acc) {
    __syncthreads();
    #pragma unroll 4
    for (int i = tid; i < 2048; i += 256) {
        int r = i >> 3, jq = (i & 7) * 4;
        float4 v = *(const float4*)&g_x[(r0 + r) * 256 + CC * 32 + jq];
        *(float4*)&xs[r * 36 + jq] = v;
    }
    __syncthreads();
    JL<CC * 32, 0>::run(xs + tid * 36, acc);
}

// ---------------- fwd w-DFT: thread-per-row, FFMA-imm twiddles (R6, measured good) ----------------
__global__ void __launch_bounds__(256) k_fwd_w_imm() {
    __shared__ float xs[256 * 36];
    int tid = threadIdx.x, r0 = blockIdx.x * 256;
    float2 acc[16];
    #pragma unroll
    for (int k = 0; k < 16; k++) acc[k] = make_float2(0.f, 0.f);
    fw_chunk<0>(tid, r0, xs, acc);
    fw_chunk<1>(tid, r0, xs, acc);
    fw_chunk<2>(tid, r0, xs, acc);
    fw_chunk<3>(tid, r0, xs, acc);
    fw_chunk<4>(tid, r0, xs, acc);
    fw_chunk<5>(tid, r0, xs, acc);
    fw_chunk<6>(tid, r0, xs, acc);
    fw_chunk<7>(tid, r0, xs, acc);
    float* gp = g_G + (r0 + tid) * 32;
    #pragma unroll
    for (int k = 0; k < 8; k++) {
        float4 v = make_float4(acc[2 * k].x, acc[2 * k].y, acc[2 * k + 1].x, acc[2 * k + 1].y);
        *(float4*)&gp[4 * k] = v;
    }
}

// ---------------- init: fp32 twiddle tables ----------------
__global__ void k_init() {
    int tid = threadIdx.x;
    double s, c;
    sincospi((double)tid / 128.0, &s, &c);
    g_ct[tid] = (float)c;  g_st[tid] = (float)s;
    g_cc2[tid] = make_float2((float)c, (float)c);
    g_ss2[tid] = make_float2((float)s, (float)s);
}

// ---------------- one-time weight transpose: [l][i][o][m][kx] -> [l][mode][i*64+o] ----------------
__global__ void __launch_bounds__(256) k_wprep(const float* __restrict__ w1r, const float* __restrict__ w1i,
                                               const float* __restrict__ w2r, const float* __restrict__ w2i) {
    __shared__ float tile[32][257];
    int bx = blockIdx.x;
    int l = bx & 3, src = (bx >> 2) & 3, io0 = (bx >> 4) * 32;
    const float* sp;
    if      (src == 0) sp = w1r;
    else if (src == 1) sp = w1i;
    else if (src == 2) sp = w2r;
    else               sp = w2i;
    sp += (long)l * 1048576 + (long)io0 * 256;
    int t = threadIdx.x;
    #pragma unroll 4
    for (int io = 0; io < 32; io++) tile[io][t] = sp[io * 256 + t];
    __syncthreads();
    float* tp = ((src & 1) ? g_Wti : g_Wtr) + (long)l * 2097152 + ((src >= 2) ? (long)256 * 4096 : 0) + io0;
    int lane = t & 31, row = t >> 5;
    #pragma unroll 4
    for (int j = 0; j < 32; j++) {
        int m = row + j * 8;
        tp[(long)m * 4096 + lane] = tile[lane][m];
    }
}

// ---------------- lift (R6 scalar) ----------------
__global__ void __launch_bounds__(256) k_lift(const float* __restrict__ grid,
                                              const float* __restrict__ lw,
                                              const float* __restrict__ lb) {
    __shared__ float sw[960], sb[64];
    for (int i = threadIdx.x; i < 960; i += 256) sw[i] = lw[i];
    if (threadIdx.x < 64) sb[threadIdx.x] = lb[threadIdx.x];
    __syncthreads();
    int p = blockIdx.x * 256 + threadIdx.x;
    int b = p >> 16, hw = p & 65535;
    float in[15];
    const float* gp = grid + b * 15 * HWn + hw;
    #pragma unroll
    for (int c = 0; c < 15; c++) in[c] = gp[c * HWn];
    float* xp = g_x + b * Cn * HWn + hw;
    for (int o = 0; o < 64; o++) {
        float a = sb[o];
        #pragma unroll
        for (int c = 0; c < 15; c++) a = fmaf(in[c], sw[o * 15 + c], a);
        xp[o * HWn] = gelu(a);
    }
}

// ---------------- fwd h-DFT (R2 scalar compute; mode-major scatter output) ----------------
__global__ void __launch_bounds__(256) k_fwd_h() {
    __shared__ float Gs[8192];
    int tid = threadIdx.x, bc = blockIdx.x;
    const float* gp = g_G + bc * 8192;
    for (int i = tid; i < 8192; i += 256) Gs[i] = gp[i];
    __syncthreads();
    int s = tid >> 3, kq = tid & 7;
    int ky = (s < 16) ? s : s + 224;
    float cd = g_ct[ky], sd = -g_st[ky], cw = 1.f, sw = 0.f;
    float fr0 = 0.f, fi0 = 0.f, fr1 = 0.f, fi1 = 0.f;
    for (int h = 0; h < 256; h++) {
        float2 g0 = *(const float2*)&Gs[h * 32 + kq * 4];
        float2 g1 = *(const float2*)&Gs[h * 32 + kq * 4 + 2];
        fr0 = fmaf(g0.x, cw, fmaf(-g0.y, sw, fr0));
        fi0 = fmaf(g0.y, cw, fmaf( g0.x, sw, fi0));
        fr1 = fmaf(g1.x, cw, fmaf(-g1.y, sw, fr1));
        fi1 = fmaf(g1.y, cw, fmaf( g1.x, sw, fi1));
        float cn = cw * cd - sw * sd;
        sw = fmaf(cw, sd, sw * cd);  cw = cn;
    }
    int m0 = s * 16 + kq * 2;
    g_F[m0 * 2048 + bc]              = fr0;
    g_F[m0 * 2048 + 1024 + bc]       = fi0;
    g_F[(m0 + 1) * 2048 + bc]        = fr1;
    g_F[(m0 + 1) * 2048 + 1024 + bc] = fi1;
}

// ---------------- spectral multiply: fully coalesced loads, block per mode ----------------
__global__ void __launch_bounds__(256) k_spec(int l) {
    __shared__ float Wr[4096], Wi[4096], Ar[1024], Ai[1024];
    int m = blockIdx.x, t = threadIdx.x;
    const float* wr = g_Wtr + (long)l * 2097152 + (long)m * 4096;
    const float* wi = g_Wti + (long)l * 2097152 + (long)m * 4096;
    for (int i = t; i < 4096; i += 256) { Wr[i] = wr[i]; Wi[i] = wi[i]; }
    const float* fp = g_F + (long)m * 2048;
    for (int i = t; i < 1024; i += 256) { Ar[i] = fp[i]; Ai[i] = fp[1024 + i]; }
    __syncthreads();
    int o = t & 63, bq = t >> 6;
    float orr[4], oii[4];
    #pragma unroll
    for (int u = 0; u < 4; u++) { orr[u] = 0.f; oii[u] = 0.f; }
    for (int i = 0; i < 64; i++) {
        float wrv = Wr[i * 64 + o], wiv = Wi[i * 64 + o];
        #pragma unroll
        for (int u = 0; u < 4; u++) {
            float arv = Ar[(bq * 4 + u) * 64 + i], aiv = Ai[(bq * 4 + u) * 64 + i];
            orr[u] = fmaf(arv, wrv, fmaf(-aiv, wiv, orr[u]));
            oii[u] = fmaf(arv, wiv, fmaf( aiv, wrv, oii[u]));
        }
    }
    #pragma unroll
    for (int u = 0; u < 4; u++) {
        int b = bq * 4 + u;
        *(float2*)&g_F2[(b * 64 + o) * 1024 + m * 2] = make_float2(orr[u], oii[u]);
    }
}

// ---------------- inv h-DFT (packed, interleaved float2 output) ----------------
__global__ void __launch_bounds__(256) k_inv_h() {
    __shared__ float Fs[1024];
    __shared__ float2 scc[256], sss[256];
    int tid = threadIdx.x, bo = blockIdx.x;
    const float* fp = g_F2 + bo * 1024;
    for (int i = tid; i < 1024; i += 256) Fs[i] = fp[i];
    scc[tid] = g_cc2[tid]; sss[tid] = g_ss2[tid];
    __syncthreads();
    int h = tid;
    float2 P[16], Q[16];
    #pragma unroll
    for (int k = 0; k < 16; k++) { P[k] = make_float2(0.f, 0.f); Q[k] = make_float2(0.f, 0.f); }
    #pragma unroll 2
    for (int s = 0; s < 32; s++) {
        int ky = (s < 16) ? s : s + 224;
        int idx = (ky * h) & 255;
        float2 cc = scc[idx], ss = sss[idx];
        #pragma unroll
        for (int q = 0; q < 8; q++) {
            float4 f4 = *(const float4*)&Fs[s * 32 + q * 4];
            float2 fa = make_float2(f4.x, f4.y), fb = make_float2(f4.z, f4.w);
            P[2 * q]     = ffma2(fa, cc, P[2 * q]);     Q[2 * q]     = ffma2(fa, ss, Q[2 * q]);
            P[2 * q + 1] = ffma2(fb, cc, P[2 * q + 1]); Q[2 * q + 1] = ffma2(fb, ss, Q[2 * q + 1]);
        }
    }
    float2* go = (float2*)g_Gi + bo * 4096 + h;
    #pragma unroll
    for (int k = 0; k < 16; k++) {
        float sc = (k == 0 ? 1.f : 2.f) * (1.f / 65536.f);
        go[k * 256] = make_float2((P[k].x - Q[k].y) * sc, (P[k].y + Q[k].x) * sc);
    }
}

// ---------------- fused inv w-DFT + skip conv + BN + gelu + residual (R6, measured good) ----------------
__global__ void __launch_bounds__(256, 2) k_fuse(const float* __restrict__ skw, const float* __restrict__ skb,
                                                 const float* __restrict__ bng, const float* __restrict__ bnb,
                                                 const float* __restrict__ bnm, const float* __restrict__ bnv,
                                                 int l) {
    extern __shared__ float sm[];
    float* xs   = sm;              // 16896 = 64*264
    float* swt  = xs + 16896;      // 4096: [c][o]
    float* gis  = swt + 4096;      // 2048: [kx][ri][o], ri=1 negated
    float* ctb  = gis + 2048;      // 256
    float* stb  = ctb + 256;       // 256
    float* bnA  = stb + 256;       // 64
    float* bnB  = bnA + 64;        // 64
    float* sbbv = bnB + 64;        // 64
    int tid = threadIdx.x;
    int b = blockIdx.x >> 8, h = blockIdx.x & 255;
    float* xp = g_x + b * 64 * HWn + h * 256;
    for (int c = 0; c < 64; c++) xs[c * 264 + tid] = xp[c * HWn + tid];
    for (int i = tid; i < 4096; i += 256) {
        int o = i >> 6, c = i & 63;
        swt[c * 64 + o] = skw[l * 4096 + i];
    }
    for (int i = tid; i < 1024; i += 256) {
        int o = i >> 4, kx = i & 15;
        float2 v = ((const float2*)g_Gi)[(b * 64 + o) * 4096 + kx * 256 + h];
        gis[(kx * 2) * 64 + o]     = v.x;
        gis[(kx * 2 + 1) * 64 + o] = -v.y;
    }
    ctb[tid] = g_ct[tid];  stb[tid] = g_st[tid];
    if (tid < 64) {
        float A = bng[l * 64 + tid] * rsqrtf(bnv[l * 64 + tid] + 1e-5f);
        bnA[tid] = A;
        bnB[tid] = fmaf(-bnm[l * 64 + tid], A, bnb[l * 64 + tid]);
        sbbv[tid] = skb[l * 64 + tid];
    }
    __syncthreads();
    int wb = (tid & 63) * 4, ob = (tid >> 6) * 16;
    float2 acc[8][4];
    #pragma unroll
    for (int ip = 0; ip < 8; ip++) {
        float2 bias = *(const float2*)&sbbv[ob + ip * 2];
        acc[ip][0] = bias; acc[ip][1] = bias; acc[ip][2] = bias; acc[ip][3] = bias;
    }
    for (int c = 0; c < 64; c++) {
        float4 xv = *(const float4*)&xs[c * 264 + wb];
        float2 x0 = make_float2(xv.x, xv.x), x1 = make_float2(xv.y, xv.y);
        float2 x2 = make_float2(xv.z, xv.z), x3 = make_float2(xv.w, xv.w);
        #pragma unroll
        for (int ip = 0; ip < 8; ip++) {
            float2 wv = *(const float2*)&swt[c * 64 + ob + ip * 2];
            acc[ip][0] = ffma2(x0, wv, acc[ip][0]);
            acc[ip][1] = ffma2(x1, wv, acc[ip][1]);
            acc[ip][2] = ffma2(x2, wv, acc[ip][2]);
            acc[ip][3] = ffma2(x3, wv, acc[ip][3]);
        }
    }
    float dc[4], ds[4], tc_[4], ts_[4];
    #pragma unroll
    for (int j = 0; j < 4; j++) {
        dc[j] = ctb[wb + j];  ds[j] = stb[wb + j];
        tc_[j] = 1.f;  ts_[j] = 0.f;
    }
    #pragma unroll 4
    for (int kx = 0; kx < 16; kx++) {
        float2 cc0 = make_float2(tc_[0], tc_[0]), ss0 = make_float2(ts_[0], ts_[0]);
        float2 cc1 = make_float2(tc_[1], tc_[1]), ss1 = make_float2(ts_[1], ts_[1]);
        float2 cc2 = make_float2(tc_[2], tc_[2]), ss2 = make_float2(ts_[2], ts_[2]);
        float2 cc3 = make_float2(tc_[3], tc_[3]), ss3 = make_float2(ts_[3], ts_[3]);
        #pragma unroll
        for (int ip = 0; ip < 8; ip++) {
            float2 gr = *(const float2*)&gis[(kx * 2) * 64 + ob + ip * 2];
            float2 gi = *(const float2*)&gis[(kx * 2 + 1) * 64 + ob + ip * 2];
            acc[ip][0] = ffma2(gr, cc0, acc[ip][0]);  acc[ip][0] = ffma2(gi, ss0, acc[ip][0]);
            acc[ip][1] = ffma2(gr, cc1, acc[ip][1]);  acc[ip][1] = ffma2(gi, ss1, acc[ip][1]);
            acc[ip][2] = ffma2(gr, cc2, acc[ip][2]);  acc[ip][2] = ffma2(gi, ss2, acc[ip][2]);
            acc[ip][3] = ffma2(gr, cc3, acc[ip][3]);  acc[ip][3] = ffma2(gi, ss3, acc[ip][3]);
        }
        #pragma unroll
        for (int j = 0; j < 4; j++) {
            float nc = tc_[j] * dc[j] - ts_[j] * ds[j];
            ts_[j] = fmaf(tc_[j], ds[j], ts_[j] * dc[j]);
            tc_[j] = nc;
        }
    }
    #pragma unroll
    for (int ip = 0; ip < 8; ip++) {
        int o0 = ob + ip * 2, o1 = o0 + 1;
        float A0 = bnA[o0], B0 = bnB[o0], A1 = bnA[o1], B1 = bnB[o1];
        float4 r0, r1;
        r0.x = gelu(fmaf(acc[ip][0].x, A0, B0)) + xs[o0 * 264 + wb];
        r0.y = gelu(fmaf(acc[ip][1].x, A0, B0)) + xs[o0 * 264 + wb + 1];
        r0.z = gelu(fmaf(acc[ip][2].x, A0, B0)) + xs[o0 * 264 + wb + 2];
        r0.w = gelu(fmaf(acc[ip][3].x, A0, B0)) + xs[o0 * 264 + wb + 3];
        r1.x = gelu(fmaf(acc[ip][0].y, A1, B1)) + xs[o1 * 264 + wb];
        r1.y = gelu(fmaf(acc[ip][1].y, A1, B1)) + xs[o1 * 264 + wb + 1];
        r1.z = gelu(fmaf(acc[ip][2].y, A1, B1)) + xs[o1 * 264 + wb + 2];
        r1.w = gelu(fmaf(acc[ip][3].y, A1, B1)) + xs[o1 * 264 + wb + 3];
        *(float4*)&xp[o0 * HWn + wb] = r0;
        *(float4*)&xp[o1 * HWn + wb] = r1;
    }
}

// ---------------- proj conv + gelu + partial mean (R2 scalar) ----------------
__global__ void __launch_bounds__(256) k_proj(const float* __restrict__ pw, const float* __restrict__ pb) {
    __shared__ float pws[4096], pbs[64], wsum[64][8];
    int tid = threadIdx.x;
    int b = blockIdx.x >> 8, h = blockIdx.x & 255;
    for (int i = tid; i < 4096; i += 256) pws[i] = pw[i];
    if (tid < 64) pbs[tid] = pb[tid];
    __syncthreads();
    const float* xp = g_x + b * 64 * HWn + h * 256 + tid;
    float xv[64];
    #pragma unroll
    for (int c = 0; c < 64; c++) xv[c] = xp[c * HWn];
    int lane = tid & 31, wid = tid >> 5;
    for (int o = 0; o < 64; o++) {
        float a = pbs[o];
        #pragma unroll
        for (int c = 0; c < 64; c++) a = fmaf(xv[c], pws[o * 64 + c], a);
        a = gelu(a);
        #pragma unroll
        for (int off = 16; off; off >>= 1) a += __shfl_down_sync(0xffffffffu, a, off);
        if (lane == 0) wsum[o][wid] = a;
    }
    __syncthreads();
    if (tid < 64) {
        float s = 0.f;
        #pragma unroll
        for (int j = 0; j < 8; j++) s += wsum[tid][j];
        g_part[(b * 64 + tid) * 256 + h] = s;
    }
}

__global__ void __launch_bounds__(128) k_head(const float* __restrict__ env, const float* __restrict__ d1d,
    const float* __restrict__ dw1, const float* __restrict__ db1,
    const float* __restrict__ dw2, const float* __restrict__ db2,
    const float* __restrict__ dw3, const float* __restrict__ db3,
    const float* __restrict__ iw1, const float* __restrict__ ib1,
    const float* __restrict__ iw2, const float* __restrict__ ib2,
    const float* __restrict__ iw3, const float* __restrict__ ib3,
    float* __restrict__ out) {
    __shared__ float feat[108], h1[128], h2[64];
    int b = blockIdx.x, t = threadIdx.x;
    if (t < 64) {
        float s = 0.f;
        const float* pp = g_part + (b * 64 + t) * 256;
        for (int h = 0; h < 256; h++) s += pp[h];
        feat[t] = s * (1.0f / 65536.0f);
    } else if (t < 104) feat[t] = env[b * 40 + t - 64];
    else if (t < 108)   feat[t] = d1d[b * 4 + t - 104];
    __syncthreads();
    { float a = db1[t];
      for (int k = 0; k < 108; k++) a = fmaf(feat[k], dw1[t * 108 + k], a);
      h1[t] = gelu(a); }
    __syncthreads();
    if (t < 64) { float a = db2[t];
      for (int k = 0; k < 128; k++) a = fmaf(h1[k], dw2[t * 128 + k], a);
      h2[t] = gelu(a); }
    __syncthreads();
    if (t < 8) { float a = db3[t];
      for (int k = 0; k < 64; k++) a = fmaf(h2[k], dw3[t * 64 + k], a);
      out[b * 8 + t] = a; }
    __syncthreads();
    { float a = ib1[t];
      for (int k = 0; k < 108; k++) a = fmaf(feat[k], iw1[t * 108 + k], a);
      h1[t] = gelu(a); }
    __syncthreads();
    if (t < 64) { float a = ib2[t];
      for (int k = 0; k < 128; k++) a = fmaf(h1[k], iw2[t * 128 + k], a);
      h2[t] = gelu(a); }
    __syncthreads();
    if (t < 4) { float a = ib3[t];
      for (int k = 0; k < 64; k++) a = fmaf(h2[k], iw3[t * 64 + k], a);
      out[128 + b * 4 + t] = a; }
}

extern "C" void kernel_launch(void* const* d_in, const int* in_sizes, int n_in,
                              void* d_out, int out_size) {
    const float* grid_in = (const float*)d_in[0];
    const float* env  = (const float*)d_in[1];
    const float* d1d  = (const float*)d_in[2];
    const float* lw   = (const float*)d_in[3];
    const float* lb   = (const float*)d_in[4];
    const float* w1r  = (const float*)d_in[5];
    const float* w1i  = (const float*)d_in[6];
    const float* w2r  = (const float*)d_in[7];
    const float* w2i  = (const float*)d_in[8];
    const float* skw  = (const float*)d_in[9];
    const float* skb  = (const float*)d_in[10];
    const float* bng  = (const float*)d_in[11];
    const float* bnb  = (const float*)d_in[12];
    const float* bnm  = (const float*)d_in[13];
    const float* bnv  = (const float*)d_in[14];
    const float* pw   = (const float*)d_in[15];
    const float* pb   = (const float*)d_in[16];
    const float* dw1  = (const float*)d_in[17];
    const float* db1  = (const float*)d_in[18];
    const float* dw2  = (const float*)d_in[19];
    const float* db2  = (const float*)d_in[20];
    const float* dw3  = (const float*)d_in[21];
    const float* db3  = (const float*)d_in[22];
    const float* iw1  = (const float*)d_in[23];
    const float* ib1  = (const float*)d_in[24];
    const float* iw2  = (const float*)d_in[25];
    const float* ib2  = (const float*)d_in[26];
    const float* iw3  = (const float*)d_in[27];
    const float* ib3  = (const float*)d_in[28];
    float* out = (float*)d_out;

    static bool attr_done = false;
    if (!attr_done) {
        cudaFuncSetAttribute(k_fuse, cudaFuncAttributeMaxDynamicSharedMemorySize, 94976);
        attr_done = true;
    }

    k_init<<<1, 256>>>();
    k_wprep<<<2048, 256>>>(w1r, w1i, w2r, w2i);
    k_lift<<<4096, 256>>>(grid_in, lw, lb);
    for (int l = 0; l < 4; l++) {
        k_fwd_w_imm<<<1024, 256>>>();
        k_fwd_h<<<1024, 256>>>();
        k_spec<<<512, 256>>>(l);
        k_inv_h<<<1024, 256>>>();
        k_fuse<<<4096, 256, 94976>>>(skw, skb, bng, bnb, bnm, bnv, l);
    }
    k_proj<<<4096, 256>>>(pw, pb);
    k_head<<<16, 128>>>(env, d1d, dw1, db1, dw2, db2, dw3, db3,
                        iw1, ib1, iw2, ib2, iw3, ib3, out);
}